// round 3
// baseline (speedup 1.0000x reference)
#include <cuda_runtime.h>

// ---------------------------------------------------------------------------
// ChordProgressionLoss
//   T = 1,000,000 rows, 4 notes per row (float-encoded ints 0..127).
//   Everything reduces to 12-bit pitch-class bitmasks per row.
//   Kernel 1: one streaming pass, per-block partial sums (sim, penalty).
//   Kernel 2: deterministic double-precision final reduction -> scalar.
// ---------------------------------------------------------------------------

#define TPB 256
#define MAX_BLOCKS 4608   // supports up to ~1.18M rows at TPB=256

__device__ float g_partials[2 * MAX_BLOCKS];

// Template bitmasks
// MAJOR: (0,4,7) (5,9,0) (7,11,2) (0,4,7)
// MINOR: (0,3,7) (5,8,0) (7,10,2) (0,3,7)
__constant__ unsigned c_major[4] = {0x091u, 0x221u, 0x884u, 0x091u};
__constant__ unsigned c_minor[4] = {0x089u, 0x121u, 0x484u, 0x089u};

__device__ __forceinline__ unsigned pc_bits(const float* __restrict__ base, int row) {
    float4 v = *reinterpret_cast<const float4*>(base + 4 * (size_t)row);
    unsigned b = 0;
    b |= 1u << (((int)v.x) % 12);
    b |= 1u << (((int)v.y) % 12);
    b |= 1u << (((int)v.z) % 12);
    b |= 1u << (((int)v.w) % 12);
    return b;
}

__device__ __forceinline__ float jaccard_d(unsigned b, unsigned tmpl) {
    int inter = __popc(b & tmpl);
    int sp    = __popc(b);
    float uni = (float)(sp + 3 - inter);
    return 1.0f - (float)inter / (uni + 1e-8f);
}

__global__ __launch_bounds__(TPB)
void chord_main_kernel(const float* __restrict__ pred,
                       const float* __restrict__ targ,
                       int T) {
    __shared__ unsigned s_pb[TPB + 3];
    __shared__ float s_red[TPB / 32];

    int t = blockIdx.x * TPB + threadIdx.x;

    unsigned pb = 0;
    if (t < T) {
        pb = pc_bits(pred, t);
        s_pb[threadIdx.x] = pb;
        if (threadIdx.x < 3) {
            int t2 = t + TPB;
            s_pb[TPB + threadIdx.x] = (t2 < T) ? pc_bits(pred, t2) : 0u;
        }
    }
    __syncthreads();

    float sim = 0.0f;
    float pen = 0.0f;

    if (t < T) {
        // ---- similarity term ----
        unsigned tb = pc_bits(targ, t);
        const float eps = 1e-6f;
        float sp = (float)__popc(pb);
        float st = (float)__popc(tb);
        float in = (float)__popc(pb & tb);
        float num = in + eps * (sp + st) + 12.0f * eps * eps;
        float s   = num / ((sp + 12.0f * eps) * (st + 12.0f * eps));
        sim = fminf(fmaxf(s, 0.0f), 1.0f);

        // ---- progression penalty (window starting at t) ----
        if (t < T - 3) {
            float maj = 0.0f, mino = 0.0f;
            #pragma unroll
            for (int j = 0; j < 4; j++) {
                unsigned bj = s_pb[threadIdx.x + j];
                maj  += jaccard_d(bj, c_major[j]);
                mino += jaccard_d(bj, c_minor[j]);
            }
            pen = fminf(maj * 0.25f, mino * 0.25f);
        }
    }

    // ---- block reduction (tree: warp shuffle + smem) ----
    int lane = threadIdx.x & 31;
    int wid  = threadIdx.x >> 5;

    #pragma unroll
    for (int off = 16; off > 0; off >>= 1)
        sim += __shfl_down_sync(0xFFFFFFFFu, sim, off);
    if (lane == 0) s_red[wid] = sim;
    __syncthreads();
    if (wid == 0) {
        float v = (lane < TPB / 32) ? s_red[lane] : 0.0f;
        #pragma unroll
        for (int off = 4; off > 0; off >>= 1)
            v += __shfl_down_sync(0xFFFFFFFFu, v, off);
        if (lane == 0) g_partials[blockIdx.x] = v;
    }
    __syncthreads();

    #pragma unroll
    for (int off = 16; off > 0; off >>= 1)
        pen += __shfl_down_sync(0xFFFFFFFFu, pen, off);
    if (lane == 0) s_red[wid] = pen;
    __syncthreads();
    if (wid == 0) {
        float v = (lane < TPB / 32) ? s_red[lane] : 0.0f;
        #pragma unroll
        for (int off = 4; off > 0; off >>= 1)
            v += __shfl_down_sync(0xFFFFFFFFu, v, off);
        if (lane == 0) g_partials[MAX_BLOCKS + blockIdx.x] = v;
    }
}

__global__ __launch_bounds__(256)
void chord_final_kernel(float* __restrict__ out, int nBlocks, int T) {
    __shared__ double s_s[8], s_p[8];
    double s = 0.0, p = 0.0;
    for (int i = threadIdx.x; i < nBlocks; i += 256) {
        s += (double)g_partials[i];
        p += (double)g_partials[MAX_BLOCKS + i];
    }
    int lane = threadIdx.x & 31;
    int wid  = threadIdx.x >> 5;
    #pragma unroll
    for (int off = 16; off > 0; off >>= 1) {
        s += __shfl_down_sync(0xFFFFFFFFu, s, off);
        p += __shfl_down_sync(0xFFFFFFFFu, p, off);
    }
    if (lane == 0) { s_s[wid] = s; s_p[wid] = p; }
    __syncthreads();
    if (wid == 0) {
        s = (lane < 8) ? s_s[lane] : 0.0;
        p = (lane < 8) ? s_p[lane] : 0.0;
        #pragma unroll
        for (int off = 4; off > 0; off >>= 1) {
            s += __shfl_down_sync(0xFFFFFFFFu, s, off);
            p += __shfl_down_sync(0xFFFFFFFFu, p, off);
        }
        if (lane == 0) {
            double sim_loss = 1.0 - s / (double)T;
            double prog     = p / (double)(T - 3);
            out[0] = (float)(sim_loss + 0.5 * prog);
        }
    }
}

extern "C" void kernel_launch(void* const* d_in, const int* in_sizes, int n_in,
                              void* d_out, int out_size) {
    const float* pred = (const float*)d_in[0];
    const float* targ = (const float*)d_in[1];
    int T = in_sizes[0] / 4;

    int nBlocks = (T + TPB - 1) / TPB;
    chord_main_kernel<<<nBlocks, TPB>>>(pred, targ, T);
    chord_final_kernel<<<1, 256>>>((float*)d_out, nBlocks, T);
}